// round 14
// baseline (speedup 1.0000x reference)
#include <cuda_runtime.h>
#include <math.h>

#define BS 16
#define NQ 1024   // columns m (queries)
#define NT 128    // rows n (targets)
#define INF_F 1e9f
#define FULL 0xffffffffu

#define NOWN 256               // column-owner threads (8 warps)
#define NWARP 8                // owner warps
#define THREADS 288            // + 1 orchestrator warp
#define CPL 4                  // columns per owner thread

// ---------------------------------------------------------------------------
// Faithful Jonker-Volgenant replay, fused, zero global scratch.
// Row-data cache s_rd[j] = {tx,ty,tp,u} of row p[j]: the post-argmin chain is
// ONE LDS.128 instead of LDS p -> LDS row fields. During a Dijkstra,
// (p[j], u[p[j]]) is constant for unused j, so reads are coherent; at row end
// the orchestrator warp refreshes exactly the columns selected this Dijkstra
// (p-injectivity => that list covers every changed entry).
// ---------------------------------------------------------------------------
__global__ void __launch_bounds__(THREADS) hm_kernel(
    const float* __restrict__ qc,   // [BS, NQ, 2]
    const float* __restrict__ ql,   // [BS, NQ, 1]
    const float* __restrict__ tc,   // [BS, NT, 2]
    const float* __restrict__ tl,   // [BS, NT, 1]
    float* __restrict__ out)
{
    const int b    = blockIdx.x;
    const int tid  = threadIdx.x;
    const int lane = tid & 31;
    const int wid  = tid >> 5;
    const bool owner = (tid < NOWN);

    __shared__ float s_tx[NT + 1], s_ty[NT + 1], s_tp[NT + 1];
    __shared__ float    s_u[NT + 1];
    __shared__ int      s_p[NQ + 1];
    __shared__ unsigned s_way[NQ + 1];       // (row-epoch << 12) | j0
    __shared__ float4   s_rd[NQ + 1];        // {tx,ty,tp,u} of row p[j]
    __shared__ int      s_ulist[NQ + 1];     // columns selected this Dijkstra
    __shared__ unsigned long long s_part[2][NWARP];

    if (tid < NT) {
        s_tx[tid + 1] = tc[(b * NT + tid) * 2 + 0];
        s_ty[tid + 1] = tc[(b * NT + tid) * 2 + 1];
        s_tp[tid + 1] = tl[b * NT + tid];
    }
    for (int j = tid; j <= NQ; j += THREADS) { s_p[j] = 0; s_way[j] = 0u; }
    for (int r = tid; r <= NT; r += THREADS) s_u[r] = 0.0f;
    if (tid == 0) s_p[0] = 1;

    const int coff  = tid * CPL;       // first owned column (0-based)
    const int jbase = coff + 1;        // first owned column (1-based)

    float qx[CPL], qy[CPL], qs[CPL];
    if (owner) {
#pragma unroll
        for (int k = 0; k < CPL; k++) {
            int q = coff + k;
            qx[k] = qc[(b * NQ + q) * 2 + 0];
            qy[k] = qc[(b * NQ + q) * 2 + 1];
            qs[k] = 1.0f / (1.0f + expf(-ql[b * NQ + q]));
        }
    }

    // cost vs current row data (registers rtx,rty,rtp); exact ref op sequence
#define COSTK(k)                                                          \
    __fadd_rn(__fmul_rn(5.0f,                                             \
        __fadd_rn(fabsf(__fadd_rn(qx[k], -rtx)),                          \
                  fabsf(__fadd_rn(qy[k], -rty)))),                        \
        fabsf(__fadd_rn(qs[k], -rtp)))

    float v[CPL], mv[CPL], u_local[CPL];
    int   pj_reg[CPL];
#pragma unroll
    for (int k = 0; k < CPL; k++) { v[k] = 0.0f; mv[k] = INF_F; }

    __syncthreads();

    int      i     = 1;        // outer row (fresh free row)
    int      j0    = 0;        // 0 => fresh relax (no way writes)
    unsigned umask = 0u;
    float    rtx = s_tx[1], rty = s_ty[1], rtp = s_tp[1], rui = 0.0f;
    float    u_acc = 0.0f;     // orchestrator: u[p[0]] accumulator
    int      gs = 0, cnt = 0;  // cnt: per-Dijkstra selection count (orch)

    for (;;) {
        if (owner) {
            // ---- relax against current row (pure registers) ----
            if (j0 == 0) {
#pragma unroll
                for (int k = 0; k < CPL; k++) {
                    float cur = COSTK(k) - rui - v[k];
                    if (cur < mv[k]) mv[k] = cur;           // way = 0 implicit
                }
            } else {
                unsigned wtag = ((unsigned)i << 12) | (unsigned)j0;
#pragma unroll
                for (int k = 0; k < CPL; k++) {
                    if (!((umask >> k) & 1u)) {
                        float cur = COSTK(k) - rui - v[k];
                        if (cur < mv[k]) { mv[k] = cur; s_way[jbase + k] = wtag; }
                    }
                }
            }

            // ---- local argmin (lowest idx wins ties) ----
            float tv0 = ((umask >> 0) & 1u) ? INF_F : mv[0];
            float tv1 = ((umask >> 1) & 1u) ? INF_F : mv[1];
            float tv2 = ((umask >> 2) & 1u) ? INF_F : mv[2];
            float tv3 = ((umask >> 3) & 1u) ? INF_F : mv[3];
            int ti0 = jbase, ti2 = jbase + 2;
            if (tv1 < tv0) { tv0 = tv1; ti0 = jbase + 1; }
            if (tv3 < tv2) { tv2 = tv3; ti2 = jbase + 3; }
            if (tv2 < tv0) { tv0 = tv2; ti0 = ti2; }

            // ---- warp argmin via redux (lexicographic: val, then j) ----
            float cv = tv0 + 0.0f;                          // -0 -> +0
            unsigned ub  = __float_as_uint(cv);
            unsigned key = (ub & 0x80000000u) ? ~ub : (ub | 0x80000000u);
            unsigned mk  = __reduce_min_sync(FULL, key);
            unsigned ci  = (key == mk) ? (unsigned)ti0 : 0xffffffffu;
            unsigned jw  = __reduce_min_sync(FULL, ci);
            if (lane == 0)
                s_part[gs & 1][wid] = ((unsigned long long)mk << 32) | jw;
        }
        __syncthreads();

        // ---- combine partials (all threads identically) ----
        unsigned long long best = s_part[gs & 1][0];
#pragma unroll
        for (int w = 1; w < NWARP; w++) {
            unsigned long long p64 = s_part[gs & 1][w];
            if (p64 < best) best = p64;
        }
        gs++;
        const int j1 = (int)(unsigned)best;
        unsigned gk  = (unsigned)(best >> 32);
        unsigned du  = (gk & 0x80000000u) ? (gk ^ 0x80000000u) : ~gk;
        const float delta = __uint_as_float(du);

        const int    i0n  = s_p[j1];          // LDS (parallel w/ s_rd)
        const float4 rd   = s_rd[j1];         // LDS.128: {tx,ty,tp,u} of p[j1]
        const bool   done = (i0n == 0);

        if (owner) {
            // ---- dual updates (j1 still 'unused'; reference order) ----
#pragma unroll
            for (int k = 0; k < CPL; k++) {
                if ((umask >> k) & 1u) {
                    v[k]       -= delta;
                    u_local[k] += delta;
                } else {
                    mv[k] -= delta;
                }
            }
            if (!done) {
                if ((unsigned)(j1 - 1) / CPL == (unsigned)tid) {
                    int kk = (j1 - 1) & (CPL - 1);
#pragma unroll
                    for (int k = 0; k < CPL; k++) {
                        if (k == kk) {
                            umask |= 1u << k;
                            pj_reg[k]  = i0n;
                            u_local[k] = rd.w;   // u[i0n] pre-entry value
                        }
                    }
                }
                rtx = rd.x; rty = rd.y; rtp = rd.z; rui = rd.w;
                j0 = j1;
            } else {
                // flush u of my used columns (distinct rows: race-free)
#pragma unroll
                for (int k = 0; k < CPL; k++)
                    if ((umask >> k) & 1u) s_u[pj_reg[k]] = u_local[k];
            }
        } else {
            u_acc += delta;
            if (lane == 0) s_ulist[cnt] = j1;   // record selection (incl final)
            cnt++;
            if (done && tid == NOWN) s_u[i] = u_acc;  // fresh row's u
        }

        if (done) {
            __syncthreads();   // A: all u flushed before orch reads them
            if (owner) {
                if (i == NT) break;
                i++;
#pragma unroll
                for (int k = 0; k < CPL; k++) mv[k] = INF_F;
                umask = 0u; j0 = 0;
                rtx = s_tx[i]; rty = s_ty[i]; rtp = s_tp[i]; rui = 0.0f;
            } else {
                if (tid == NOWN) {
                    // augment along epoch-tagged way[] (s_p[0] == i)
                    int jj = j1;
                    do {
                        unsigned w  = s_way[jj];
                        int      jn = ((w >> 12) == (unsigned)i)
                                      ? (int)(w & 0xFFFu) : 0;
                        s_p[jj] = s_p[jn];
                        jj = jn;
                    } while (jj != 0);
                    s_p[0] = i + 1;           // for next Dijkstra
                }
                __syncwarp();                  // p updates visible in warp
                // refresh s_rd for every column selected this Dijkstra
                for (int l = lane; l < cnt; l += 32) {
                    int jj = s_ulist[l];
                    int pj = s_p[jj];
                    s_rd[jj] = make_float4(s_tx[pj], s_ty[pj],
                                           s_tp[pj], s_u[pj]);
                }
                if (i == NT) break;
                i++;
                u_acc = 0.0f; cnt = 0;
            }
        }
    }
#undef COSTK
    __syncthreads();   // final augment + rd refresh visible

    // ---- output (warp 0): ballot compaction, ascending query ids ----
    if (wid == 0) {
        int base = 0;
        for (int c = 0; c < 32; c++) {
            int j  = c * 32 + lane + 1;
            int pi = s_p[j];
            bool m = pi > 0;
            unsigned bal = __ballot_sync(FULL, m);
            int pos = base + __popc(bal & ((1u << lane) - 1u));
            if (m) {
                out[b * NT + pos]           = (float)(j - 1);   // rows (query)
                out[BS * NT + b * NT + pos] = (float)(pi - 1);  // cols (target)
            }
            base += __popc(bal);
        }
    }
}

// ---------------------------------------------------------------------------
extern "C" void kernel_launch(void* const* d_in, const int* in_sizes, int n_in,
                              void* d_out, int out_size)
{
    // Identify inputs by element count (robust to ordering).
    const float *qc = 0, *ql = 0, *tc = 0, *tl = 0;
    for (int i = 0; i < n_in; i++) {
        switch (in_sizes[i]) {
            case 32768: qc = (const float*)d_in[i]; break;
            case 16384: ql = (const float*)d_in[i]; break;
            case 4096:  tc = (const float*)d_in[i]; break;
            case 2048:  tl = (const float*)d_in[i]; break;
        }
    }

    hm_kernel<<<BS, THREADS>>>(qc, ql, tc, tl, (float*)d_out);
}